// round 13
// baseline (speedup 1.0000x reference)
#include <cuda_runtime.h>

#define B_  128
#define L_  200
#define NT  25600      // B_*L_
#define D_  128
#define M_  64

// ---------------- scratch (device globals; no allocation allowed) ----------
__device__ float g_w[NT * M_];      // softmax weights      (B,L,64)
__device__ float g_e[NT * D_];      // erase gate           (B,L,128)
__device__ float g_a[NT * D_];      // add vector           (B,L,128)
__device__ float g_k[NT * D_];      // gathered k           (B,L,128)
__device__ float g_reads[NT * D_];  // scan reads           (B,L,128)
__device__ float g_diff[NT];        // question difficulty  (B,L)

__device__ __forceinline__ float sigmoidf_(float x) {
    return 1.0f / (1.0f + __expf(-x));
}

// XOR swizzle for conflict-free strided LDS.128
__device__ __forceinline__ int swz(int row, int col, int Wlog2) {
    return (row << Wlog2) + (((col >> 2) ^ (row & 7)) << 2) + (col & 3);
}

// ---- packed f32x2 helpers -------------------------------------------------
typedef unsigned long long u64;
union F4U2 { float4 f4; ulonglong2 u2; };

__device__ __forceinline__ void fma2(u64& acc, u64 a, u64 b) {
    asm("fma.rn.f32x2 %0, %1, %2, %0;" : "+l"(acc) : "l"(a), "l"(b));
}
__device__ __forceinline__ void fma2o(u64& d, u64 a, u64 b, u64 c) {
    asm("fma.rn.f32x2 %0, %1, %2, %3;" : "=l"(d) : "l"(a), "l"(b), "l"(c));
}
__device__ __forceinline__ u64 add2(u64 a, u64 b) {
    u64 d; asm("add.rn.f32x2 %0, %1, %2;" : "=l"(d) : "l"(a), "l"(b)); return d;
}
__device__ __forceinline__ u64 pack2(float lo, float hi) {
    u64 d; asm("mov.b64 %0, {%1, %2};" : "=l"(d) : "f"(lo), "f"(hi)); return d;
}
__device__ __forceinline__ float red2(u64 v) {
    float lo, hi;
    asm("mov.b64 {%0, %1}, %2;" : "=f"(lo), "=f"(hi) : "l"(v));
    return lo + hi;
}

// ============================================================================
// Kernel A: 32-row tiles; gather (cross-tile prefetched) + logits/softmax +
// e + a + diff. 512 threads, minBlocks=1, batched LDS + FFMA2.
// ============================================================================
__global__ void __launch_bounds__(512, 1) kernelA(
    const int*   __restrict__ q,    const int*   __restrict__ rsel,
    const float* __restrict__ k_emb, const float* __restrict__ v_emb,
    const float* __restrict__ Mk,
    const float* __restrict__ e_W,  const float* __restrict__ e_b,
    const float* __restrict__ a_W,  const float* __restrict__ a_b,
    const float* __restrict__ df_W, const float* __restrict__ df_b)
{
    extern __shared__ float sm[];
    float* Mk_s    = sm;                    // 64*128
    float* eW_s    = Mk_s + 64 * 128;       // 128*128
    float* aW_s    = eW_s + 128 * 128;      // 128*128
    float* dfW_s   = aW_s + 128 * 128;      // 128
    float* vemb_s  = dfW_s + 128;           // 2*128
    float* k_s     = vemb_s + 256;          // 32*128
    float* v_s     = k_s + 4096;            // 32*128
    float* logit_s = v_s + 4096;            // 32*64

    const int tid = threadIdx.x;
    const int NTILES = NT / 32;             // 800

    for (int i = tid; i < 64 * 128; i += 512) {
        int row = i >> 7, col = i & 127;
        Mk_s[swz(row, col, 7)] = Mk[i];
    }
    for (int i = tid; i < 128 * 128; i += 512) {
        int row = i >> 7, col = i & 127;
        int s = swz(row, col, 7);
        eW_s[s] = e_W[i];
        aW_s[s] = a_W[i];
    }
    if (tid < 128)      dfW_s[tid]       = df_W[tid];
    else if (tid < 384) vemb_s[tid - 128] = v_emb[tid - 128];

    const float dfb = df_b[0];
    const int dA = tid & 127;
    const float ebd = e_b[dA];
    const float abd = a_b[dA];

    const float4* Mk4 = (const float4*)Mk_s;
    const float4* eW4 = (const float4*)eW_s;
    const float4* aW4 = (const float4*)aW_s;
    const float4* v4  = (const float4*)v_s;
    const float4* k4  = (const float4*)k_s;

    // ---- prefetch first tile's gather into registers ----
    int g = blockIdx.x;
    float kv[8];
    unsigned rbits = 0;
    {
        const int base = g * 32;
        #pragma unroll
        for (int u = 0; u < 8; u++) {
            int rl = (tid >> 7) + u * 4;
            int qi = q[base + rl];
            rbits |= ((unsigned)rsel[base + rl] & 1u) << u;
            kv[u] = k_emb[qi * 128 + dA];
        }
    }
    __syncthreads();   // also covers weight/vemb staging

    for (; g < NTILES; g += gridDim.x) {
        const int base = g * 32;

        // ---- store prefetched tile to smem / spill k to global ----
        #pragma unroll
        for (int u = 0; u < 8; u++) {
            int i = tid + u * 512;
            int rl = (tid >> 7) + u * 4;
            float k0 = kv[u];
            k_s[i] = k0;
            v_s[i] = k0 + vemb_s[((rbits >> u) & 1u) * 128 + dA];
            g_k[(base + rl) * 128 + dA] = k0;
        }
        __syncthreads();

        // ---- prefetch NEXT tile's gather (latency hidden by compute) ----
        const int gn = g + gridDim.x;
        if (gn < NTILES) {
            const int bn = gn * 32;
            rbits = 0;
            #pragma unroll
            for (int u = 0; u < 8; u++) {
                int rl = (tid >> 7) + u * 4;
                int qi = q[bn + rl];
                rbits |= ((unsigned)rsel[bn + rl] & 1u) << u;
                kv[u] = k_emb[qi * 128 + dA];
            }
        }

        // ---- logits: thread = (m, rowgroup rgl of 4 rows), rgl 0..7 ----
        {
            const int m = tid & 63, rgl = tid >> 6;
            const int mb = m & 7;
            const float4* ka = k4 + (rgl * 4) * 32;
            u64 acc[4];
            #pragma unroll
            for (int r = 0; r < 4; r++) acc[r] = 0ull;
            #pragma unroll 4
            for (int dd = 0; dd < 32; dd++) {
                F4U2 mm, kk[4];
                mm.f4 = Mk4[(m << 5) + (dd ^ mb)];
                #pragma unroll
                for (int r = 0; r < 4; r++) kk[r].f4 = ka[r * 32 + dd];
                #pragma unroll
                for (int r = 0; r < 4; r++) {
                    fma2(acc[r], kk[r].u2.x, mm.u2.x);
                    fma2(acc[r], kk[r].u2.y, mm.u2.y);
                }
            }
            #pragma unroll
            for (int r = 0; r < 4; r++)
                logit_s[(rgl * 4 + r) * 64 + m] = red2(acc[r]);
        }

        // ---- e & a: thread = (d, rowgroup rge of 8 rows), rge 0..3 ----
        {
            const int d = dA, rge = tid >> 7;
            const int db = d & 7;
            const float4* vb = v4 + (rge * 8) * 32;
            u64 ae[8], aa[8];
            #pragma unroll
            for (int r = 0; r < 8; r++) { ae[r] = 0ull; aa[r] = 0ull; }
            #pragma unroll 2
            for (int jj = 0; jj < 32; jj++) {
                const int s = (d << 5) + (jj ^ db);
                F4U2 we, wa, vv[8];
                we.f4 = eW4[s];
                wa.f4 = aW4[s];
                #pragma unroll
                for (int r = 0; r < 8; r++) vv[r].f4 = vb[r * 32 + jj];
                #pragma unroll
                for (int r = 0; r < 8; r++) {
                    fma2(ae[r], vv[r].u2.x, we.u2.x);
                    fma2(ae[r], vv[r].u2.y, we.u2.y);
                    fma2(aa[r], vv[r].u2.x, wa.u2.x);
                    fma2(aa[r], vv[r].u2.y, wa.u2.y);
                }
            }
            #pragma unroll
            for (int r = 0; r < 8; r++) {
                int r0 = (base + rge * 8 + r) * 128 + d;
                g_e[r0] = sigmoidf_(red2(ae[r]) + ebd);
                g_a[r0] = tanhf(red2(aa[r]) + abd);
            }
        }
        __syncthreads();

        // ---- epilogue: 16 warps, warp w handles rows 2w, 2w+1 ----
        {
            const int w = tid >> 5, lane = tid & 31;
            #pragma unroll
            for (int rr = 0; rr < 2; rr++) {
                const int row = w * 2 + rr;
                float x0 = logit_s[(row << 6) + lane];
                float x1 = logit_s[(row << 6) + 32 + lane];
                float mx = fmaxf(x0, x1);
                #pragma unroll
                for (int o = 16; o; o >>= 1) mx = fmaxf(mx, __shfl_xor_sync(~0u, mx, o));
                float e0 = __expf(x0 - mx), e1 = __expf(x1 - mx);
                float s = e0 + e1;
                #pragma unroll
                for (int o = 16; o; o >>= 1) s += __shfl_xor_sync(~0u, s, o);
                float inv = 1.f / s;
                int gw = (base + row) * 64;
                g_w[gw + lane]      = e0 * inv;
                g_w[gw + 32 + lane] = e1 * inv;

                const float* kp = k_s + (row << 7);
                float acc = kp[lane]      * dfW_s[lane]
                          + kp[lane + 32] * dfW_s[lane + 32]
                          + kp[lane + 64] * dfW_s[lane + 64]
                          + kp[lane + 96] * dfW_s[lane + 96];
                #pragma unroll
                for (int o = 16; o; o >>= 1) acc += __shfl_xor_sync(~0u, acc, o);
                if (lane == 0) g_diff[base + row] = tanhf(acc + dfb);
            }
        }
        __syncthreads();   // protect k_s/v_s before next tile's STS
    }
}

// ============================================================================
// Kernel B (measured-good): ZERO-sync scan. 128 blocks x 128 threads; thread
// owns column d with ALL 64 Mv[m,d] in registers (32 packed u64).
// ============================================================================
__global__ void __launch_bounds__(128, 1) kernelB(const float* __restrict__ Mv0)
{
    const int d = threadIdx.x;     // 0..127
    const int b = blockIdx.x;

    const float* wrow = g_w + b * L_ * M_;
    const float* erow = g_e + b * L_ * D_ + d;
    const float* arow = g_a + b * L_ * D_ + d;
    float*       rrow = g_reads + b * L_ * D_ + d;

    u64 Mv2[32];
    #pragma unroll
    for (int i = 0; i < 32; i++) {
        Mv2[i] = pack2(Mv0[(2 * i) * D_ + d], Mv0[(2 * i + 1) * D_ + d]);
    }

    ulonglong2 wA[16], wB[16];
    {
        const ulonglong2* w0 = (const ulonglong2*)wrow;
        #pragma unroll
        for (int i = 0; i < 16; i++) wA[i] = w0[i];
    }
    float e_c = erow[0],  a_c = arow[0];
    float e_n = erow[D_], a_n = arow[D_];

#define SCAN_STEP(WCUR, WNXT, T)                                              \
    {                                                                          \
        if ((T) + 1 < L_) {                                                    \
            const ulonglong2* wq = (const ulonglong2*)(wrow + ((T) + 1) * 64); \
            _Pragma("unroll")                                                  \
            for (int i = 0; i < 16; i++) WNXT[i] = wq[i];                      \
        }                                                                      \
        const u64 ne2 = pack2(-e_c, -e_c);                                     \
        const u64 a2  = pack2(a_c,  a_c);                                      \
        u64 pa[4] = {0ull, 0ull, 0ull, 0ull};                                  \
        _Pragma("unroll")                                                      \
        for (int i = 0; i < 16; i++) {                                         \
            u64 w0 = WCUR[i].x, w1 = WCUR[i].y;                                \
            u64 m0 = Mv2[2 * i], m1 = Mv2[2 * i + 1];                          \
            fma2(pa[(2 * i) & 3], w0, m0);                                     \
            fma2(pa[(2 * i + 1) & 3], w1, m1);                                 \
            u64 t0, t1;                                                        \
            fma2o(t0, ne2, m0, a2);                                            \
            fma2o(t1, ne2, m1, a2);                                            \
            fma2o(Mv2[2 * i],     w0, t0, m0);                                 \
            fma2o(Mv2[2 * i + 1], w1, t1, m1);                                 \
        }                                                                      \
        rrow[(T) * D_] = red2(add2(add2(pa[0], pa[1]), add2(pa[2], pa[3])));   \
        e_c = e_n; a_c = a_n;                                                  \
        if ((T) + 2 < L_) { e_n = erow[((T) + 2) * D_]; a_n = arow[((T) + 2) * D_]; } \
    }

    #pragma unroll 1
    for (int t = 0; t < L_; t += 2) {
        SCAN_STEP(wA, wB, t);
        SCAN_STEP(wB, wA, t + 1);
    }
#undef SCAN_STEP
}

// ============================================================================
// Kernel C: 64-row tiles with cross-tile prefetch of the cat tile;
// thread = (column pair dd/dd+64, rowgroup of 8 rows). 512 threads, FFMA2.
// ============================================================================
__global__ void __launch_bounds__(512, 1) kernelC(
    const float* __restrict__ f_W, const float* __restrict__ f_b,
    const float* __restrict__ ab_W, const float* __restrict__ ab_b,
    float* __restrict__ out)
{
    extern __shared__ float sm[];
    float* fW_s  = sm;                 // 128*256
    float* cat_s = fW_s + 128 * 256;   // 64*256
    float* red_s = cat_s + 16384;      // 16 warps * 8 rows

    const int tid = threadIdx.x;
    const int NTILES = NT / 64;        // 400
    for (int i = tid; i < 128 * 256; i += 512) {
        int row = i >> 8, col = i & 255;
        fW_s[swz(row, col, 8)] = f_W[i];
    }

    const float abb = ab_b[0];
    const int d2 = tid & 63, rg = tid >> 6;     // rg 0..7, 8 rows each
    const int dd0 = d2, dd1 = d2 + 64;
    const float fb0 = f_b[dd0], fb1 = f_b[dd1];
    const float aw0 = ab_W[dd0], aw1 = ab_W[dd1];
    const int db = d2 & 7;                      // == dd1 & 7
    const int wid = tid >> 5, lane = tid & 31;

    const float4* fW4 = (const float4*)fW_s;
    const float4* c4  = (const float4*)cat_s;
    const float4* gr4 = (const float4*)g_reads;
    const float4* gk4 = (const float4*)g_k;
    float4* cat4 = (float4*)cat_s;

    // prefetch first tile
    int g = blockIdx.x;
    float4 pre[8];
    {
        const int base = g * 64;
        #pragma unroll
        for (int u = 0; u < 8; u++) {
            int i = tid + u * 512;
            int rl = i >> 6, c = i & 63;
            int row = base + rl;
            pre[u] = (c < 32) ? gr4[row * 32 + c] : gk4[row * 32 + (c - 32)];
        }
    }
    __syncthreads();   // weights staged

    for (; g < NTILES; g += gridDim.x) {
        const int base = g * 64;

        #pragma unroll
        for (int u = 0; u < 8; u++) cat4[tid + u * 512] = pre[u];
        __syncthreads();

        const int gn = g + gridDim.x;
        if (gn < NTILES) {
            const int bn = gn * 64;
            #pragma unroll
            for (int u = 0; u < 8; u++) {
                int i = tid + u * 512;
                int rl = i >> 6, c = i & 63;
                int row = bn + rl;
                pre[u] = (c < 32) ? gr4[row * 32 + c] : gk4[row * 32 + (c - 32)];
            }
        }

        const float4* cb = c4 + (rg * 8) * 64;
        u64 ac0[8], ac1[8];
        #pragma unroll
        for (int r = 0; r < 8; r++) { ac0[r] = 0ull; ac1[r] = 0ull; }
        #pragma unroll 2
        for (int jj = 0; jj < 64; jj++) {
            F4U2 w0, w1, cc[8];
            w0.f4 = fW4[(dd0 << 6) + (jj ^ db)];
            w1.f4 = fW4[(dd1 << 6) + (jj ^ db)];
            #pragma unroll
            for (int r = 0; r < 8; r++) cc[r].f4 = cb[r * 64 + jj];
            #pragma unroll
            for (int r = 0; r < 8; r++) {
                fma2(ac0[r], cc[r].u2.x, w0.u2.x);
                fma2(ac0[r], cc[r].u2.y, w0.u2.y);
                fma2(ac1[r], cc[r].u2.x, w1.u2.x);
                fma2(ac1[r], cc[r].u2.y, w1.u2.y);
            }
        }

        float p[8];
        #pragma unroll
        for (int r = 0; r < 8; r++) {
            float f0 = tanhf(red2(ac0[r]) + fb0);
            float f1 = tanhf(red2(ac1[r]) + fb1);
            p[r] = f0 * aw0 + f1 * aw1;
        }
        #pragma unroll
        for (int o = 16; o; o >>= 1) {
            #pragma unroll
            for (int r = 0; r < 8; r++)
                p[r] += __shfl_xor_sync(~0u, p[r], o);
        }
        if (lane == 0) {
            #pragma unroll
            for (int r = 0; r < 8; r++) red_s[wid * 8 + r] = p[r];
        }
        __syncthreads();
        if (tid < 64) {
            const int rgg = tid >> 3, r = tid & 7;
            float s = red_s[(rgg * 2) * 8 + r] + red_s[(rgg * 2 + 1) * 8 + r];
            float ability = tanhf(s + abb);
            out[base + tid] = sigmoidf_(3.f * ability - g_diff[base + tid]);
        }
        __syncthreads();   // protect cat_s/red_s before next iteration
    }
}

// ============================================================================
extern "C" void kernel_launch(void* const* d_in, const int* in_sizes, int n_in,
                              void* d_out, int out_size)
{
    (void)in_sizes; (void)n_in; (void)out_size;
    const int*   q     = (const int*)  d_in[0];
    const int*   rsel  = (const int*)  d_in[1];
    const float* k_emb = (const float*)d_in[2];
    const float* v_emb = (const float*)d_in[3];
    const float* Mk    = (const float*)d_in[4];
    const float* Mv0   = (const float*)d_in[5];
    const float* f_W   = (const float*)d_in[6];
    const float* f_b   = (const float*)d_in[7];
    const float* e_W   = (const float*)d_in[8];
    const float* e_b   = (const float*)d_in[9];
    const float* a_W   = (const float*)d_in[10];
    const float* a_b   = (const float*)d_in[11];
    const float* ab_W  = (const float*)d_in[12];
    const float* ab_b  = (const float*)d_in[13];
    const float* df_W  = (const float*)d_in[14];
    const float* df_b  = (const float*)d_in[15];
    float* out = (float*)d_out;

    const int smA = (64 * 128 + 2 * 128 * 128 + 128 + 256 + 4096 + 4096 + 2048) * 4;
    const int smC = (128 * 256 + 64 * 256 + 128) * 4;
    cudaFuncSetAttribute(kernelA, cudaFuncAttributeMaxDynamicSharedMemorySize, smA);
    cudaFuncSetAttribute(kernelC, cudaFuncAttributeMaxDynamicSharedMemorySize, smC);

    kernelA<<<148, 512, smA>>>(q, rsel, k_emb, v_emb, Mk, e_W, e_b,
                               a_W, a_b, df_W, df_b);
    kernelB<<<128, 128>>>(Mv0);
    kernelC<<<148, 512, smC>>>(f_W, f_b, ab_W, ab_b, out);
}

// round 15
// speedup vs baseline: 1.1622x; 1.1622x over previous
#include <cuda_runtime.h>
#include <cstdint>

#define B_  128
#define L_  200
#define NT  25600      // B_*L_
#define D_  128
#define M_  64

// ---------------- scratch (device globals; no allocation allowed) ----------
__device__ float g_w[NT * M_];      // softmax weights      (B,L,64)
__device__ float g_e[NT * D_];      // erase gate           (B,L,128)
__device__ float g_a[NT * D_];      // add vector           (B,L,128)
__device__ float g_k[NT * D_];      // gathered k           (B,L,128)
__device__ float g_reads[NT * D_];  // scan reads           (B,L,128)
__device__ float g_diff[NT];        // question difficulty  (B,L)

__device__ __forceinline__ float sigmoidf_(float x) {
    return 1.0f / (1.0f + __expf(-x));
}

// XOR swizzle for conflict-free strided LDS.128
__device__ __forceinline__ int swz(int row, int col, int Wlog2) {
    return (row << Wlog2) + (((col >> 2) ^ (row & 7)) << 2) + (col & 3);
}

// ---- packed f32x2 helpers -------------------------------------------------
typedef unsigned long long u64;
union F4U2 { float4 f4; ulonglong2 u2; };

__device__ __forceinline__ void fma2(u64& acc, u64 a, u64 b) {
    asm("fma.rn.f32x2 %0, %1, %2, %0;" : "+l"(acc) : "l"(a), "l"(b));
}
__device__ __forceinline__ void fma2o(u64& d, u64 a, u64 b, u64 c) {
    asm("fma.rn.f32x2 %0, %1, %2, %3;" : "=l"(d) : "l"(a), "l"(b), "l"(c));
}
__device__ __forceinline__ u64 add2(u64 a, u64 b) {
    u64 d; asm("add.rn.f32x2 %0, %1, %2;" : "=l"(d) : "l"(a), "l"(b)); return d;
}
__device__ __forceinline__ u64 pack2(float lo, float hi) {
    u64 d; asm("mov.b64 %0, {%1, %2};" : "=l"(d) : "f"(lo), "f"(hi)); return d;
}
__device__ __forceinline__ float red2(u64 v) {
    float lo, hi;
    asm("mov.b64 {%0, %1}, %2;" : "=f"(lo), "=f"(hi) : "l"(v));
    return lo + hi;
}

// ---- mma.sync tf32 m16n8k8 (base PTX, compiles for sm_103) ----------------
__device__ __forceinline__ void mma_tf32(float* d, const uint32_t* a,
                                         uint32_t b0, uint32_t b1) {
    asm volatile(
        "mma.sync.aligned.m16n8k8.row.col.f32.tf32.tf32.f32 "
        "{%0,%1,%2,%3}, {%4,%5,%6,%7}, {%8,%9}, {%0,%1,%2,%3};"
        : "+f"(d[0]), "+f"(d[1]), "+f"(d[2]), "+f"(d[3])
        : "r"(a[0]), "r"(a[1]), "r"(a[2]), "r"(a[3]), "r"(b0), "r"(b1));
}

// ============================================================================
// Kernel A (measured 89us): 32-row tiles; gather (cross-tile prefetched) +
// logits/softmax + e + a + diff. 512 threads, minBlocks=1, FFMA2.
// ============================================================================
__global__ void __launch_bounds__(512, 1) kernelA(
    const int*   __restrict__ q,    const int*   __restrict__ rsel,
    const float* __restrict__ k_emb, const float* __restrict__ v_emb,
    const float* __restrict__ Mk,
    const float* __restrict__ e_W,  const float* __restrict__ e_b,
    const float* __restrict__ a_W,  const float* __restrict__ a_b,
    const float* __restrict__ df_W, const float* __restrict__ df_b)
{
    extern __shared__ float sm[];
    float* Mk_s    = sm;                    // 64*128
    float* eW_s    = Mk_s + 64 * 128;       // 128*128
    float* aW_s    = eW_s + 128 * 128;      // 128*128
    float* dfW_s   = aW_s + 128 * 128;      // 128
    float* vemb_s  = dfW_s + 128;           // 2*128
    float* k_s     = vemb_s + 256;          // 32*128
    float* v_s     = k_s + 4096;            // 32*128
    float* logit_s = v_s + 4096;            // 32*64

    const int tid = threadIdx.x;
    const int NTILES = NT / 32;             // 800

    for (int i = tid; i < 64 * 128; i += 512) {
        int row = i >> 7, col = i & 127;
        Mk_s[swz(row, col, 7)] = Mk[i];
    }
    for (int i = tid; i < 128 * 128; i += 512) {
        int row = i >> 7, col = i & 127;
        int s = swz(row, col, 7);
        eW_s[s] = e_W[i];
        aW_s[s] = a_W[i];
    }
    if (tid < 128)      dfW_s[tid]        = df_W[tid];
    else if (tid < 384) vemb_s[tid - 128] = v_emb[tid - 128];

    const float dfb = df_b[0];
    const int dA = tid & 127;
    const float ebd = e_b[dA];
    const float abd = a_b[dA];

    const float4* Mk4 = (const float4*)Mk_s;
    const float4* eW4 = (const float4*)eW_s;
    const float4* aW4 = (const float4*)aW_s;
    const float4* v4  = (const float4*)v_s;
    const float4* k4  = (const float4*)k_s;

    int g = blockIdx.x;
    float kv[8];
    unsigned rbits = 0;
    {
        const int base = g * 32;
        #pragma unroll
        for (int u = 0; u < 8; u++) {
            int rl = (tid >> 7) + u * 4;
            int qi = q[base + rl];
            rbits |= ((unsigned)rsel[base + rl] & 1u) << u;
            kv[u] = k_emb[qi * 128 + dA];
        }
    }
    __syncthreads();

    for (; g < NTILES; g += gridDim.x) {
        const int base = g * 32;

        #pragma unroll
        for (int u = 0; u < 8; u++) {
            int i = tid + u * 512;
            int rl = (tid >> 7) + u * 4;
            float k0 = kv[u];
            k_s[i] = k0;
            v_s[i] = k0 + vemb_s[((rbits >> u) & 1u) * 128 + dA];
            g_k[(base + rl) * 128 + dA] = k0;
        }
        __syncthreads();

        const int gn = g + gridDim.x;
        if (gn < NTILES) {
            const int bn = gn * 32;
            rbits = 0;
            #pragma unroll
            for (int u = 0; u < 8; u++) {
                int rl = (tid >> 7) + u * 4;
                int qi = q[bn + rl];
                rbits |= ((unsigned)rsel[bn + rl] & 1u) << u;
                kv[u] = k_emb[qi * 128 + dA];
            }
        }

        {
            const int m = tid & 63, rgl = tid >> 6;
            const int mb = m & 7;
            const float4* ka = k4 + (rgl * 4) * 32;
            u64 acc[4];
            #pragma unroll
            for (int r = 0; r < 4; r++) acc[r] = 0ull;
            #pragma unroll 4
            for (int dd = 0; dd < 32; dd++) {
                F4U2 mm, kk[4];
                mm.f4 = Mk4[(m << 5) + (dd ^ mb)];
                #pragma unroll
                for (int r = 0; r < 4; r++) kk[r].f4 = ka[r * 32 + dd];
                #pragma unroll
                for (int r = 0; r < 4; r++) {
                    fma2(acc[r], kk[r].u2.x, mm.u2.x);
                    fma2(acc[r], kk[r].u2.y, mm.u2.y);
                }
            }
            #pragma unroll
            for (int r = 0; r < 4; r++)
                logit_s[(rgl * 4 + r) * 64 + m] = red2(acc[r]);
        }

        {
            const int d = dA, rge = tid >> 7;
            const int db = d & 7;
            const float4* vb = v4 + (rge * 8) * 32;
            u64 ae[8], aa[8];
            #pragma unroll
            for (int r = 0; r < 8; r++) { ae[r] = 0ull; aa[r] = 0ull; }
            #pragma unroll 2
            for (int jj = 0; jj < 32; jj++) {
                const int s = (d << 5) + (jj ^ db);
                F4U2 we, wa, vv[8];
                we.f4 = eW4[s];
                wa.f4 = aW4[s];
                #pragma unroll
                for (int r = 0; r < 8; r++) vv[r].f4 = vb[r * 32 + jj];
                #pragma unroll
                for (int r = 0; r < 8; r++) {
                    fma2(ae[r], vv[r].u2.x, we.u2.x);
                    fma2(ae[r], vv[r].u2.y, we.u2.y);
                    fma2(aa[r], vv[r].u2.x, wa.u2.x);
                    fma2(aa[r], vv[r].u2.y, wa.u2.y);
                }
            }
            #pragma unroll
            for (int r = 0; r < 8; r++) {
                int r0 = (base + rge * 8 + r) * 128 + d;
                g_e[r0] = sigmoidf_(red2(ae[r]) + ebd);
                g_a[r0] = tanhf(red2(aa[r]) + abd);
            }
        }
        __syncthreads();

        {
            const int w = tid >> 5, lane = tid & 31;
            #pragma unroll
            for (int rr = 0; rr < 2; rr++) {
                const int row = w * 2 + rr;
                float x0 = logit_s[(row << 6) + lane];
                float x1 = logit_s[(row << 6) + 32 + lane];
                float mx = fmaxf(x0, x1);
                #pragma unroll
                for (int o = 16; o; o >>= 1) mx = fmaxf(mx, __shfl_xor_sync(~0u, mx, o));
                float e0 = __expf(x0 - mx), e1 = __expf(x1 - mx);
                float s = e0 + e1;
                #pragma unroll
                for (int o = 16; o; o >>= 1) s += __shfl_xor_sync(~0u, s, o);
                float inv = 1.f / s;
                int gw = (base + row) * 64;
                g_w[gw + lane]      = e0 * inv;
                g_w[gw + 32 + lane] = e1 * inv;

                const float* kp = k_s + (row << 7);
                float acc = kp[lane]      * dfW_s[lane]
                          + kp[lane + 32] * dfW_s[lane + 32]
                          + kp[lane + 64] * dfW_s[lane + 64]
                          + kp[lane + 96] * dfW_s[lane + 96];
                #pragma unroll
                for (int o = 16; o; o >>= 1) acc += __shfl_xor_sync(~0u, acc, o);
                if (lane == 0) g_diff[base + row] = tanhf(acc + dfb);
            }
        }
        __syncthreads();
    }
}

// ============================================================================
// Kernel B (measured-good): ZERO-sync scan. 128 blocks x 128 threads.
// ============================================================================
__global__ void __launch_bounds__(128, 1) kernelB(const float* __restrict__ Mv0)
{
    const int d = threadIdx.x;
    const int b = blockIdx.x;

    const float* wrow = g_w + b * L_ * M_;
    const float* erow = g_e + b * L_ * D_ + d;
    const float* arow = g_a + b * L_ * D_ + d;
    float*       rrow = g_reads + b * L_ * D_ + d;

    u64 Mv2[32];
    #pragma unroll
    for (int i = 0; i < 32; i++) {
        Mv2[i] = pack2(Mv0[(2 * i) * D_ + d], Mv0[(2 * i + 1) * D_ + d]);
    }

    ulonglong2 wA[16], wB[16];
    {
        const ulonglong2* w0 = (const ulonglong2*)wrow;
        #pragma unroll
        for (int i = 0; i < 16; i++) wA[i] = w0[i];
    }
    float e_c = erow[0],  a_c = arow[0];
    float e_n = erow[D_], a_n = arow[D_];

#define SCAN_STEP(WCUR, WNXT, T)                                              \
    {                                                                          \
        if ((T) + 1 < L_) {                                                    \
            const ulonglong2* wq = (const ulonglong2*)(wrow + ((T) + 1) * 64); \
            _Pragma("unroll")                                                  \
            for (int i = 0; i < 16; i++) WNXT[i] = wq[i];                      \
        }                                                                      \
        const u64 ne2 = pack2(-e_c, -e_c);                                     \
        const u64 a2  = pack2(a_c,  a_c);                                      \
        u64 pa[4] = {0ull, 0ull, 0ull, 0ull};                                  \
        _Pragma("unroll")                                                      \
        for (int i = 0; i < 16; i++) {                                         \
            u64 w0 = WCUR[i].x, w1 = WCUR[i].y;                                \
            u64 m0 = Mv2[2 * i], m1 = Mv2[2 * i + 1];                          \
            fma2(pa[(2 * i) & 3], w0, m0);                                     \
            fma2(pa[(2 * i + 1) & 3], w1, m1);                                 \
            u64 t0, t1;                                                        \
            fma2o(t0, ne2, m0, a2);                                            \
            fma2o(t1, ne2, m1, a2);                                            \
            fma2o(Mv2[2 * i],     w0, t0, m0);                                 \
            fma2o(Mv2[2 * i + 1], w1, t1, m1);                                 \
        }                                                                      \
        rrow[(T) * D_] = red2(add2(add2(pa[0], pa[1]), add2(pa[2], pa[3])));   \
        e_c = e_n; a_c = a_n;                                                  \
        if ((T) + 2 < L_) { e_n = erow[((T) + 2) * D_]; a_n = arow[((T) + 2) * D_]; } \
    }

    #pragma unroll 1
    for (int t = 0; t < L_; t += 2) {
        SCAN_STEP(wA, wB, t);
        SCAN_STEP(wB, wA, t + 1);
    }
#undef SCAN_STEP
}

// ============================================================================
// Kernel C v3: mma.sync tf32 GEMM (base PTX HMMA). 64-row tiles.
// D[64,128] = cat[64,256] @ f_W^T. 16 warps, each owns 16 rows x 32 cols
// (1 m-tile x 4 n-tiles, 32 k-steps of m16n8k8). Operands in smem with
// stride-260 padding (conflict-free fragment loads). ~197KB smem.
// ============================================================================
#define CT_ROWS  64
#define CT_TILES (NT / CT_ROWS)    // 400
#define CSTR     260               // padded row stride (floats)

__global__ void __launch_bounds__(512, 1) kernelC(
    const float* __restrict__ f_W, const float* __restrict__ f_b,
    const float* __restrict__ ab_W, const float* __restrict__ ab_b,
    float* __restrict__ out)
{
    extern __shared__ float sm[];
    float* fW_s  = sm;                    // 128 * 260
    float* cat_s = fW_s + 128 * CSTR;     // 64 * 260
    float* red_s = cat_s + 64 * CSTR;     // 64 * 4

    const int tid  = threadIdx.x;
    const int wid  = tid >> 5, lane = tid & 31;
    const int gr   = lane >> 2, gt = lane & 3;   // fragment group row / col
    const int warpM = wid & 3;                   // 16-row block   (0..3)
    const int warpN = wid >> 2;                  // 32-col block   (0..3)

    // stage f_W [128 x 256] with padded stride
    for (int i = tid; i < 128 * 256; i += 512) {
        int row = i >> 8, col = i & 255;
        fW_s[row * CSTR + col] = f_W[i];
    }

    // per-thread bias / ab_W at this thread's 8 n-columns
    const float abb = ab_b[0];
    float fb[8], aw[8];
    #pragma unroll
    for (int nt = 0; nt < 4; nt++) {
        int n = warpN * 32 + nt * 8 + 2 * gt;
        fb[nt * 2]     = f_b[n];
        fb[nt * 2 + 1] = f_b[n + 1];
        aw[nt * 2]     = ab_W[n];
        aw[nt * 2 + 1] = ab_W[n + 1];
    }

    const float4* gr4 = (const float4*)g_reads;
    const float4* gk4 = (const float4*)g_k;

    // prefetch first tile's cat into registers
    int g = blockIdx.x;
    float4 pre[8];
    {
        const int base = g * CT_ROWS;
        #pragma unroll
        for (int u = 0; u < 8; u++) {
            int i = tid + u * 512;           // 0..4095
            int row = i >> 6, c4 = i & 63;
            pre[u] = (c4 < 32) ? gr4[(base + row) * 32 + c4]
                               : gk4[(base + row) * 32 + (c4 - 32)];
        }
    }
    __syncthreads();   // f_W staged

    const float* aptr = cat_s + (warpM * 16 + gr) * CSTR + gt;
    const float* bptr = fW_s + (warpN * 32 + gr) * CSTR + gt;

    for (; g < CT_TILES; g += gridDim.x) {
        const int base = g * CT_ROWS;

        #pragma unroll
        for (int u = 0; u < 8; u++) {
            int i = tid + u * 512;
            int row = i >> 6, c4 = i & 63;
            *(float4*)(cat_s + row * CSTR + c4 * 4) = pre[u];
        }
        __syncthreads();

        const int gn = g + gridDim.x;
        if (gn < CT_TILES) {
            const int bn = gn * CT_ROWS;
            #pragma unroll
            for (int u = 0; u < 8; u++) {
                int i = tid + u * 512;
                int row = i >> 6, c4 = i & 63;
                pre[u] = (c4 < 32) ? gr4[(bn + row) * 32 + c4]
                                   : gk4[(bn + row) * 32 + (c4 - 32)];
            }
        }

        // ---- GEMM: 32 k-steps of m16n8k8, 4 n-tiles ----
        float acc[4][4];
        #pragma unroll
        for (int nt = 0; nt < 4; nt++)
            #pragma unroll
            for (int e = 0; e < 4; e++) acc[nt][e] = 0.f;

        #pragma unroll 4
        for (int ks = 0; ks < 32; ks++) {
            const int kb = ks * 8;
            uint32_t a[4];
            a[0] = __float_as_uint(aptr[kb]);
            a[1] = __float_as_uint(aptr[8 * CSTR + kb]);
            a[2] = __float_as_uint(aptr[kb + 4]);
            a[3] = __float_as_uint(aptr[8 * CSTR + kb + 4]);
            #pragma unroll
            for (int nt = 0; nt < 4; nt++) {
                uint32_t b0 = __float_as_uint(bptr[nt * 8 * CSTR + kb]);
                uint32_t b1 = __float_as_uint(bptr[nt * 8 * CSTR + kb + 4]);
                mma_tf32(acc[nt], a, b0, b1);
            }
        }

        // ---- epilogue: tanh + ab_W dot, reduce over n ----
        float p0 = 0.f, p1 = 0.f;
        #pragma unroll
        for (int nt = 0; nt < 4; nt++) {
            p0 += tanhf(acc[nt][0] + fb[nt * 2])     * aw[nt * 2]
                + tanhf(acc[nt][1] + fb[nt * 2 + 1]) * aw[nt * 2 + 1];
            p1 += tanhf(acc[nt][2] + fb[nt * 2])     * aw[nt * 2]
                + tanhf(acc[nt][3] + fb[nt * 2 + 1]) * aw[nt * 2 + 1];
        }
        p0 += __shfl_xor_sync(~0u, p0, 1);
        p0 += __shfl_xor_sync(~0u, p0, 2);
        p1 += __shfl_xor_sync(~0u, p1, 1);
        p1 += __shfl_xor_sync(~0u, p1, 2);
        if (gt == 0) {
            int row = warpM * 16 + gr;
            red_s[row * 4 + warpN]       = p0;
            red_s[(row + 8) * 4 + warpN] = p1;
        }
        __syncthreads();
        if (tid < 64) {
            float s = red_s[tid * 4] + red_s[tid * 4 + 1]
                    + red_s[tid * 4 + 2] + red_s[tid * 4 + 3];
            float ability = tanhf(s + abb);
            out[base + tid] = sigmoidf_(3.f * ability - g_diff[base + tid]);
        }
        __syncthreads();   // protect cat_s/red_s before next iteration
    }
}

// ============================================================================
extern "C" void kernel_launch(void* const* d_in, const int* in_sizes, int n_in,
                              void* d_out, int out_size)
{
    (void)in_sizes; (void)n_in; (void)out_size;
    const int*   q     = (const int*)  d_in[0];
    const int*   rsel  = (const int*)  d_in[1];
    const float* k_emb = (const float*)d_in[2];
    const float* v_emb = (const float*)d_in[3];
    const float* Mk    = (const float*)d_in[4];
    const float* Mv0   = (const float*)d_in[5];
    const float* f_W   = (const float*)d_in[6];
    const float* f_b   = (const float*)d_in[7];
    const float* e_W   = (const float*)d_in[8];
    const float* e_b   = (const float*)d_in[9];
    const float* a_W   = (const float*)d_in[10];
    const float* a_b   = (const float*)d_in[11];
    const float* ab_W  = (const float*)d_in[12];
    const float* ab_b  = (const float*)d_in[13];
    const float* df_W  = (const float*)d_in[14];
    const float* df_b  = (const float*)d_in[15];
    float* out = (float*)d_out;

    const int smA = (64 * 128 + 2 * 128 * 128 + 128 + 256 + 4096 + 4096 + 2048) * 4;
    const int smC = (128 * CSTR + 64 * CSTR + 256) * 4;
    cudaFuncSetAttribute(kernelA, cudaFuncAttributeMaxDynamicSharedMemorySize, smA);
    cudaFuncSetAttribute(kernelC, cudaFuncAttributeMaxDynamicSharedMemorySize, smC);

    kernelA<<<148, 512, smA>>>(q, rsel, k_emb, v_emb, Mk, e_W, e_b,
                               a_W, a_b, df_W, df_b);
    kernelB<<<128, 128>>>(Mv0);
    kernelC<<<148, 512, smC>>>(f_W, f_b, ab_W, ab_b, out);
}